// round 13
// baseline (speedup 1.0000x reference)
#include <cuda_runtime.h>

#define NB 16
#define NN 4096
#define ND 64
#define NPOINT 1024
#define NSAMP 32
#define C0 67
#define O0 64
#define O1 64
#define O2 128
#define OUT_XYZ (NB*NPOINT*3)
#define GPB 8

// smem strides (mlp, R5 layout)
#define S0 67   // W0 row stride
#define S1 65   // W1 row stride (odd -> conflict-free)
#define SH 68   // activation row stride
#define SG 132  // maxpool scratch stride

// -------- device scratch (no allocations allowed) --------
__device__ int   g_fps[NB * NPOINT];
__device__ int   g_grp[NB * NPOINT * NSAMP];
__device__ float g_W0f[O0 * C0];                 // [o][c]
__device__ float g_b0f[O0];
__device__ float g_W1f[O1 * O0];                 // [o][c]
__device__ float g_b1f[O1];
__device__ __align__(16) float g_W2t[O1 * O2];   // transposed [c][o]
__device__ float g_b2f[O2];

// ---- packed f32x2 helpers (each lane: exact fp32 rn ops) ----
#define PACK2(out, lo, hi) \
    asm("mov.b64 %0, {%1, %2};" : "=l"(out) : "f"(lo), "f"(hi))
#define UNPACK2(lo, hi, in) \
    asm("mov.b64 {%0, %1}, %2;" : "=f"(lo), "=f"(hi) : "l"(in))
#define ADD2(out, a, b) \
    asm("add.rn.f32x2 %0, %1, %2;" : "=l"(out) : "l"(a), "l"(b))
#define MUL2(out, a, b) \
    asm("mul.rn.f32x2 %0, %1, %2;" : "=l"(out) : "l"(a), "l"(b))
#define FMA2(out, a, b, c) \
    asm("fma.rn.f32x2 %0, %1, %2, %3;" : "=l"(out) : "l"(a), "l"(b), "l"(c))

// ===================== BN fold =====================
__global__ void fold_kernel(
    const float* __restrict__ W0, const float* __restrict__ b0, const float* __restrict__ g0,
    const float* __restrict__ be0, const float* __restrict__ m0, const float* __restrict__ v0,
    const float* __restrict__ W1, const float* __restrict__ b1, const float* __restrict__ g1,
    const float* __restrict__ be1, const float* __restrict__ m1, const float* __restrict__ v1,
    const float* __restrict__ W2, const float* __restrict__ b2, const float* __restrict__ g2,
    const float* __restrict__ be2, const float* __restrict__ m2, const float* __restrict__ v2)
{
    int t = threadIdx.x;
    int nt = blockDim.x;
    for (int e = t; e < O0 * C0; e += nt) {
        int o = e / C0;
        g_W0f[e] = W0[e] * (g0[o] * rsqrtf(v0[o] + 1e-5f));
    }
    for (int e = t; e < O1 * O0; e += nt) {
        int o = e >> 6;
        g_W1f[e] = W1[e] * (g1[o] * rsqrtf(v1[o] + 1e-5f));
    }
    for (int e = t; e < O2 * O1; e += nt) {
        int c = e >> 7;          // 0..63
        int o = e & 127;         // 0..127
        g_W2t[e] = W2[o * O1 + c] * (g2[o] * rsqrtf(v2[o] + 1e-5f));
    }
    for (int o = t; o < O0; o += nt)
        g_b0f[o] = (b0[o] - m0[o]) * (g0[o] * rsqrtf(v0[o] + 1e-5f)) + be0[o];
    for (int o = t; o < O1; o += nt)
        g_b1f[o] = (b1[o] - m1[o]) * (g1[o] * rsqrtf(v1[o] + 1e-5f)) + be1[o];
    for (int o = t; o < O2; o += nt)
        g_b2f[o] = (b2[o] - m2[o]) * (g2[o] * rsqrtf(v2[o] + 1e-5f)) + be2[o];
}

// ===================== FPS =====================
// 512 threads, 8 pts/thread (R10 distance ordering, bit-identical selections).
// Per-point tracking via pure fmaxf running max (1 instr/pt); index recovered
// once per iteration by ascending-pi scan of register dl[] (first-max-index
// semantics preserved exactly). Two-level 32-bit REDUX reduction, one barrier.
__global__ __launch_bounds__(512) void fps_kernel(const float* __restrict__ xyz)
{
    __shared__ unsigned swv[2][16];
    __shared__ unsigned swi[2][16];

    int b = blockIdx.x;
    int t = threadIdx.x;
    int w = t >> 5;
    int lane = t & 31;
    const float* p = xyz + (size_t)b * NN * 3;

    float dl[8];
    unsigned long long px2[4], py2[4], pz2[4];
#pragma unroll
    for (int j = 0; j < 4; j++) {
        int p0 = t + (2 * j) * 512;
        int p1 = t + (2 * j + 1) * 512;
        float x0 = p[3 * p0], y0 = p[3 * p0 + 1], z0 = p[3 * p0 + 2];
        float x1 = p[3 * p1], y1 = p[3 * p1 + 1], z1 = p[3 * p1 + 2];
        PACK2(px2[j], x0, x1);
        PACK2(py2[j], y0, y1);
        PACK2(pz2[j], z0, z1);
        dl[2 * j] = 1e10f;
        dl[2 * j + 1] = 1e10f;
    }
    if (t == 0) g_fps[b * NPOINT] = 0;

    float cx = p[0], cy = p[1], cz = p[2];
    for (int it = 1; it < NPOINT; it++) {
        unsigned long long ncx2, ncy2, ncz2;
        {
            float nx = -cx, ny = -cy, nz = -cz;
            PACK2(ncx2, nx, nx);
            PACK2(ncy2, ny, ny);
            PACK2(ncz2, nz, nz);
        }
        float bv = -1.0f;
#pragma unroll
        for (int j = 0; j < 4; j++) {
            unsigned long long dxp, dyp, dzp, dp;
            ADD2(dxp, px2[j], ncx2);          // x - cx  (== x + (-cx), exact)
            ADD2(dyp, py2[j], ncy2);
            ADD2(dzp, pz2[j], ncz2);
            MUL2(dp, dxp, dxp);
            FMA2(dp, dyp, dyp, dp);
            FMA2(dp, dzp, dzp, dp);
            float d0, d1;
            UNPACK2(d0, d1, dp);
            float dn0 = fminf(dl[2 * j], d0);
            dl[2 * j] = dn0;
            bv = fmaxf(bv, dn0);
            float dn1 = fminf(dl[2 * j + 1], d1);
            dl[2 * j + 1] = dn1;
            bv = fmaxf(bv, dn1);
        }
        // index recovery: first (ascending pi) dl slot equal to bv.
        // pi = t + i*512, ascending in i -> scan i descending with selects.
        int bi = t + 7 * 512;
#pragma unroll
        for (int i = 6; i >= 0; i--)
            bi = (dl[i] == bv) ? (t + i * 512) : bi;
        // in-warp argmax: REDUX max on value bits (nonneg -> monotonic),
        // REDUX min over candidate indices (first-index ties exact).
        unsigned vb = __float_as_uint(bv);
        unsigned wmax = __reduce_max_sync(0xffffffffu, vb);
        unsigned cand = (vb == wmax) ? (unsigned)bi : 0xffffffffu;
        unsigned widx = __reduce_min_sync(0xffffffffu, cand);
        int par = it & 1;
        if (lane == 0) {
            swv[par][w] = wmax;
            swi[par][w] = widx;
        }
        __syncthreads();
        // cross-warp: lanes 0-15 map to warp slots (16-31 duplicate; harmless
        // for max/min). Two 32-bit REDUX passes, no second barrier (parity buf).
        unsigned sv = swv[par][lane & 15];
        unsigned gmax = __reduce_max_sync(0xffffffffu, sv);
        unsigned c2 = (sv == gmax) ? swi[par][lane & 15] : 0xffffffffu;
        unsigned idx = __reduce_min_sync(0xffffffffu, c2);
        cx = p[3 * idx]; cy = p[3 * idx + 1]; cz = p[3 * idx + 2];  // uniform L1-hit
        if (t == 0) g_fps[b * NPOINT + it] = (int)idx;
    }
}

// ===================== ball query (+new_xyz write) =====================
__global__ __launch_bounds__(256) void ballquery_kernel(const float* __restrict__ xyz,
                                                        float* __restrict__ out)
{
    int gw = (blockIdx.x * 256 + threadIdx.x) >> 5;
    int lane = threadIdx.x & 31;
    if (gw >= NB * NPOINT) return;
    int b = gw >> 10;
    const float* p = xyz + (size_t)b * NN * 3;

    int ci = g_fps[gw];
    float cx = p[3 * ci + 0];
    float cy = p[3 * ci + 1];
    float cz = p[3 * ci + 2];
    if (lane < 3) out[(size_t)gw * 3 + lane] = p[3 * ci + lane];

    float sn = fmaf(cz, cz, fmaf(cy, cy, __fmul_rn(cx, cx)));
    int* grp = g_grp + (size_t)gw * NSAMP;

    int cnt = 0;
    int first = ci;
    bool gotfirst = false;
    for (int base = 0; base < NN && cnt < NSAMP; base += 32) {
        int i = base + lane;
        float x = p[3 * i + 0], y = p[3 * i + 1], z = p[3 * i + 2];
        float sp = fmaf(z, z, fmaf(y, y, __fmul_rn(x, x)));
        float dt = fmaf(cz, z, fmaf(cy, y, __fmul_rn(cx, x)));
        float d2 = fmaf(-2.0f, dt, sn + sp);
        bool isin = !(d2 > 0.04f);
        unsigned m = __ballot_sync(0xffffffffu, isin);
        if (!gotfirst && m) { first = base + __ffs(m) - 1; gotfirst = true; }
        int pos = cnt + __popc(m & ((1u << lane) - 1u));
        if (isin && pos < NSAMP) grp[pos] = i;
        cnt += __popc(m);
    }
    if (cnt < NSAMP) {
        int p0 = cnt + lane;
        if (p0 < NSAMP) grp[p0] = first;
    }
}

// ===================== fused gather + MLP(3) + maxpool =====================
// R5 version verbatim (measured 595-599 us three times — frozen best).
__global__ __launch_bounds__(128) void mlp_kernel(const float* __restrict__ xyz,
                                                  const float* __restrict__ pts,
                                                  float* __restrict__ out)
{
    __shared__ float sW0[O0 * S0];     // 4288 floats
    __shared__ float sW1[O1 * S1];     // 4160
    __shared__ float sb[256 + O2];     // [0,64)=b0 [64,128)=b1 [128,256)=b2
    __shared__ float hin[NSAMP * SH];  // 2176 ; reused as gmax[8][SG]
    __shared__ int   sidx[NSAMP];
    __shared__ float scen[3];

    int t = threadIdx.x;
    int kt = t >> 4;   // 0..7  (k = kt + 8*i)
    int ot = t & 15;   // 0..15

    for (int e = t; e < O0 * C0; e += 128) sW0[e] = g_W0f[e];
    for (int e = t; e < O1 * O0; e += 128) sW1[(e >> 6) * S1 + (e & 63)] = g_W1f[e];
    if (t < 64)       sb[t] = g_b0f[t];
    else              sb[t] = g_b1f[t - 64];
    for (int e = t; e < O2; e += 128) sb[128 + e] = g_b2f[e];
    __syncthreads();

    for (int g = 0; g < GPB; g++) {
        int gw = blockIdx.x * GPB + g;
        int b = gw >> 10;
        const float* pxyz = xyz + (size_t)b * NN * 3;
        const float* ppts = pts + (size_t)b * NN * ND;

        if (t < NSAMP) sidx[t] = g_grp[(size_t)gw * NSAMP + t];
        if (t < 3)     scen[t] = out[(size_t)gw * 3 + t];
        __syncthreads();

        // gather: hin[k][c] = c<3 ? xyz[id][c]-cen[c] : points[id][c-3]
        for (int e = t; e < NSAMP * C0; e += 128) {
            int k = e / C0;
            int c = e - k * C0;
            int id = sidx[k];
            float v;
            if (c < 3) v = pxyz[3 * id + c] - scen[c];
            else       v = ppts[(size_t)id * ND + (c - 3)];
            hin[k * SH + c] = v;
        }
        __syncthreads();

        // ---- Layer 0: [32,67] x W0[64,67]^T ; regs -> writeback into hin ----
        {
            float acc[4][4] = {};
            for (int c = 0; c < C0; c++) {
                float a[4], w[4];
#pragma unroll
                for (int i = 0; i < 4; i++) a[i] = hin[(kt + 8 * i) * SH + c];
#pragma unroll
                for (int j = 0; j < 4; j++) w[j] = sW0[(ot + 16 * j) * S0 + c];
#pragma unroll
                for (int i = 0; i < 4; i++)
#pragma unroll
                    for (int j = 0; j < 4; j++) acc[i][j] = fmaf(a[i], w[j], acc[i][j]);
            }
            __syncthreads();   // all reads of hin done
#pragma unroll
            for (int i = 0; i < 4; i++)
#pragma unroll
                for (int j = 0; j < 4; j++) {
                    int k = kt + 8 * i, o = ot + 16 * j;
                    hin[k * SH + o] = fmaxf(acc[i][j] + sb[o], 0.0f);
                }
        }
        __syncthreads();

        // ---- Layer 1: [32,64] x W1[64,64]^T ; regs -> writeback into hin ----
        {
            float acc[4][4] = {};
            for (int c = 0; c < O0; c++) {
                float a[4], w[4];
#pragma unroll
                for (int i = 0; i < 4; i++) a[i] = hin[(kt + 8 * i) * SH + c];
#pragma unroll
                for (int j = 0; j < 4; j++) w[j] = sW1[(ot + 16 * j) * S1 + c];
#pragma unroll
                for (int i = 0; i < 4; i++)
#pragma unroll
                    for (int j = 0; j < 4; j++) acc[i][j] = fmaf(a[i], w[j], acc[i][j]);
            }
            __syncthreads();
#pragma unroll
            for (int i = 0; i < 4; i++)
#pragma unroll
                for (int j = 0; j < 4; j++) {
                    int k = kt + 8 * i, o = ot + 16 * j;
                    hin[k * SH + o] = fmaxf(acc[i][j] + sb[64 + o], 0.0f);
                }
        }
        __syncthreads();

        // ---- Layer 2: [32,64] x W2t (global, transposed, float4, L1-resident),
        //      then max over k ----
        {
            float acc[4][8] = {};
            const float4* W2v = reinterpret_cast<const float4*>(g_W2t);
            for (int c = 0; c < O1; c++) {
                float a[4];
#pragma unroll
                for (int i = 0; i < 4; i++) a[i] = hin[(kt + 8 * i) * SH + c];
                float4 w0 = __ldg(&W2v[c * 32 + ot * 2 + 0]);
                float4 w1 = __ldg(&W2v[c * 32 + ot * 2 + 1]);
                float w[8] = {w0.x, w0.y, w0.z, w0.w, w1.x, w1.y, w1.z, w1.w};
#pragma unroll
                for (int i = 0; i < 4; i++)
#pragma unroll
                    for (int j = 0; j < 8; j++) acc[i][j] = fmaf(a[i], w[j], acc[i][j]);
            }
            __syncthreads();   // hin reads done; reuse as gmax[8][SG]
            float* gmax = hin;
#pragma unroll
            for (int j = 0; j < 8; j++) {
                int o = ot * 8 + j;
                float bias = sb[128 + o];
                float pm = fmaxf(acc[0][j] + bias, 0.0f);
#pragma unroll
                for (int i = 1; i < 4; i++)
                    pm = fmaxf(pm, fmaxf(acc[i][j] + bias, 0.0f));
                gmax[kt * SG + o] = pm;
            }
            __syncthreads();
            float mx = gmax[t];
#pragma unroll
            for (int q = 1; q < 8; q++) mx = fmaxf(mx, gmax[q * SG + t]);
            out[OUT_XYZ + (size_t)gw * O2 + t] = mx;
        }
        __syncthreads();   // protect hin/sidx before next group's writes
    }
}

// ===================== launch =====================
extern "C" void kernel_launch(void* const* d_in, const int* in_sizes, int n_in,
                              void* d_out, int out_size)
{
    const float* xyz = (const float*)d_in[0];
    const float* pts = (const float*)d_in[1];
    const float* W0  = (const float*)d_in[2];
    const float* b0  = (const float*)d_in[3];
    const float* g0  = (const float*)d_in[4];
    const float* be0 = (const float*)d_in[5];
    const float* m0  = (const float*)d_in[6];
    const float* v0  = (const float*)d_in[7];
    const float* W1  = (const float*)d_in[8];
    const float* b1  = (const float*)d_in[9];
    const float* g1  = (const float*)d_in[10];
    const float* be1 = (const float*)d_in[11];
    const float* m1  = (const float*)d_in[12];
    const float* v1  = (const float*)d_in[13];
    const float* W2  = (const float*)d_in[14];
    const float* b2  = (const float*)d_in[15];
    const float* g2  = (const float*)d_in[16];
    const float* be2 = (const float*)d_in[17];
    const float* m2  = (const float*)d_in[18];
    const float* v2  = (const float*)d_in[19];
    float* out = (float*)d_out;

    // Kernel launches ONLY — graph-capturable. No dynamic smem, no attribute calls.
    fold_kernel<<<1, 256>>>(W0, b0, g0, be0, m0, v0,
                            W1, b1, g1, be1, m1, v1,
                            W2, b2, g2, be2, m2, v2);
    fps_kernel<<<NB, 512>>>(xyz);
    ballquery_kernel<<<(NB * NPOINT) / 8, 256>>>(xyz, out);
    mlp_kernel<<<(NB * NPOINT) / GPB, 128>>>(xyz, pts, out);
}

// round 14
// speedup vs baseline: 1.0719x; 1.0719x over previous
#include <cuda_runtime.h>

#define NB 16
#define NN 4096
#define ND 64
#define NPOINT 1024
#define NSAMP 32
#define C0 67
#define O0 64
#define O1 64
#define O2 128
#define OUT_XYZ (NB*NPOINT*3)
#define GPB 8

// smem strides (mlp)
#define S0 70   // W0 row stride (70/2=35 odd -> conflict-free LDS.64)
#define S1 66   // W1 row stride (66/2=33 odd -> conflict-free LDS.64)
#define SH 68   // activation row stride (even -> aligned pairs)
#define SG 132  // maxpool scratch stride

// -------- device scratch (no allocations allowed) --------
__device__ int   g_fps[NB * NPOINT];
__device__ int   g_grp[NB * NPOINT * NSAMP];
__device__ float g_W0f[O0 * C0];                 // [o][c]
__device__ float g_b0f[O0];
__device__ float g_W1f[O1 * O0];                 // [o][c]
__device__ float g_b1f[O1];
__device__ __align__(16) float g_W2t[O1 * O2];   // transposed [c][o]
__device__ float g_b2f[O2];

// ---- packed f32x2 helpers (each lane: exact fp32 rn ops) ----
#define PACK2(out, lo, hi) \
    asm("mov.b64 %0, {%1, %2};" : "=l"(out) : "f"(lo), "f"(hi))
#define UNPACK2(lo, hi, in) \
    asm("mov.b64 {%0, %1}, %2;" : "=f"(lo), "=f"(hi) : "l"(in))
#define ADD2(out, a, b) \
    asm("add.rn.f32x2 %0, %1, %2;" : "=l"(out) : "l"(a), "l"(b))
#define MUL2(out, a, b) \
    asm("mul.rn.f32x2 %0, %1, %2;" : "=l"(out) : "l"(a), "l"(b))
#define FMA2(out, a, b, c) \
    asm("fma.rn.f32x2 %0, %1, %2, %3;" : "=l"(out) : "l"(a), "l"(b), "l"(c))

// ===================== BN fold =====================
__global__ void fold_kernel(
    const float* __restrict__ W0, const float* __restrict__ b0, const float* __restrict__ g0,
    const float* __restrict__ be0, const float* __restrict__ m0, const float* __restrict__ v0,
    const float* __restrict__ W1, const float* __restrict__ b1, const float* __restrict__ g1,
    const float* __restrict__ be1, const float* __restrict__ m1, const float* __restrict__ v1,
    const float* __restrict__ W2, const float* __restrict__ b2, const float* __restrict__ g2,
    const float* __restrict__ be2, const float* __restrict__ m2, const float* __restrict__ v2)
{
    int t = threadIdx.x;
    int nt = blockDim.x;
    for (int e = t; e < O0 * C0; e += nt) {
        int o = e / C0;
        g_W0f[e] = W0[e] * (g0[o] * rsqrtf(v0[o] + 1e-5f));
    }
    for (int e = t; e < O1 * O0; e += nt) {
        int o = e >> 6;
        g_W1f[e] = W1[e] * (g1[o] * rsqrtf(v1[o] + 1e-5f));
    }
    for (int e = t; e < O2 * O1; e += nt) {
        int c = e >> 7;          // 0..63
        int o = e & 127;         // 0..127
        g_W2t[e] = W2[o * O1 + c] * (g2[o] * rsqrtf(v2[o] + 1e-5f));
    }
    for (int o = t; o < O0; o += nt)
        g_b0f[o] = (b0[o] - m0[o]) * (g0[o] * rsqrtf(v0[o] + 1e-5f)) + be0[o];
    for (int o = t; o < O1; o += nt)
        g_b1f[o] = (b1[o] - m1[o]) * (g1[o] * rsqrtf(v1[o] + 1e-5f)) + be1[o];
    for (int o = t; o < O2; o += nt)
        g_b2f[o] = (b2[o] - m2[o]) * (g2[o] * rsqrtf(v2[o] + 1e-5f)) + be2[o];
}

// ===================== FPS (R12/R13 version — measured equal, kept) ==========
__global__ __launch_bounds__(512) void fps_kernel(const float* __restrict__ xyz)
{
    __shared__ unsigned swv[2][16];
    __shared__ unsigned swi[2][16];

    int b = blockIdx.x;
    int t = threadIdx.x;
    int w = t >> 5;
    int lane = t & 31;
    const float* p = xyz + (size_t)b * NN * 3;

    float dl[8];
    unsigned long long px2[4], py2[4], pz2[4];
#pragma unroll
    for (int j = 0; j < 4; j++) {
        int p0 = t + (2 * j) * 512;
        int p1 = t + (2 * j + 1) * 512;
        float x0 = p[3 * p0], y0 = p[3 * p0 + 1], z0 = p[3 * p0 + 2];
        float x1 = p[3 * p1], y1 = p[3 * p1 + 1], z1 = p[3 * p1 + 2];
        PACK2(px2[j], x0, x1);
        PACK2(py2[j], y0, y1);
        PACK2(pz2[j], z0, z1);
        dl[2 * j] = 1e10f;
        dl[2 * j + 1] = 1e10f;
    }
    if (t == 0) g_fps[b * NPOINT] = 0;

    float cx = p[0], cy = p[1], cz = p[2];
    for (int it = 1; it < NPOINT; it++) {
        unsigned long long ncx2, ncy2, ncz2;
        {
            float nx = -cx, ny = -cy, nz = -cz;
            PACK2(ncx2, nx, nx);
            PACK2(ncy2, ny, ny);
            PACK2(ncz2, nz, nz);
        }
        float bv = -1.0f;
#pragma unroll
        for (int j = 0; j < 4; j++) {
            unsigned long long dxp, dyp, dzp, dp;
            ADD2(dxp, px2[j], ncx2);          // x - cx  (== x + (-cx), exact)
            ADD2(dyp, py2[j], ncy2);
            ADD2(dzp, pz2[j], ncz2);
            MUL2(dp, dxp, dxp);
            FMA2(dp, dyp, dyp, dp);
            FMA2(dp, dzp, dzp, dp);
            float d0, d1;
            UNPACK2(d0, d1, dp);
            float dn0 = fminf(dl[2 * j], d0);
            dl[2 * j] = dn0;
            bv = fmaxf(bv, dn0);
            float dn1 = fminf(dl[2 * j + 1], d1);
            dl[2 * j + 1] = dn1;
            bv = fmaxf(bv, dn1);
        }
        // index recovery: first (ascending pi) dl slot equal to bv.
        int bi = t + 7 * 512;
#pragma unroll
        for (int i = 6; i >= 0; i--)
            bi = (dl[i] == bv) ? (t + i * 512) : bi;
        unsigned vb = __float_as_uint(bv);
        unsigned wmax = __reduce_max_sync(0xffffffffu, vb);
        unsigned cand = (vb == wmax) ? (unsigned)bi : 0xffffffffu;
        unsigned widx = __reduce_min_sync(0xffffffffu, cand);
        int par = it & 1;
        if (lane == 0) {
            swv[par][w] = wmax;
            swi[par][w] = widx;
        }
        __syncthreads();
        unsigned sv = swv[par][lane & 15];
        unsigned gmax = __reduce_max_sync(0xffffffffu, sv);
        unsigned c2 = (sv == gmax) ? swi[par][lane & 15] : 0xffffffffu;
        unsigned idx = __reduce_min_sync(0xffffffffu, c2);
        cx = p[3 * idx]; cy = p[3 * idx + 1]; cz = p[3 * idx + 2];
        if (t == 0) g_fps[b * NPOINT + it] = (int)idx;
    }
}

// ===================== ball query (+new_xyz write) =====================
__global__ __launch_bounds__(256) void ballquery_kernel(const float* __restrict__ xyz,
                                                        float* __restrict__ out)
{
    int gw = (blockIdx.x * 256 + threadIdx.x) >> 5;
    int lane = threadIdx.x & 31;
    if (gw >= NB * NPOINT) return;
    int b = gw >> 10;
    const float* p = xyz + (size_t)b * NN * 3;

    int ci = g_fps[gw];
    float cx = p[3 * ci + 0];
    float cy = p[3 * ci + 1];
    float cz = p[3 * ci + 2];
    if (lane < 3) out[(size_t)gw * 3 + lane] = p[3 * ci + lane];

    float sn = fmaf(cz, cz, fmaf(cy, cy, __fmul_rn(cx, cx)));
    int* grp = g_grp + (size_t)gw * NSAMP;

    int cnt = 0;
    int first = ci;
    bool gotfirst = false;
    for (int base = 0; base < NN && cnt < NSAMP; base += 32) {
        int i = base + lane;
        float x = p[3 * i + 0], y = p[3 * i + 1], z = p[3 * i + 2];
        float sp = fmaf(z, z, fmaf(y, y, __fmul_rn(x, x)));
        float dt = fmaf(cz, z, fmaf(cy, y, __fmul_rn(cx, x)));
        float d2 = fmaf(-2.0f, dt, sn + sp);
        bool isin = !(d2 > 0.04f);
        unsigned m = __ballot_sync(0xffffffffu, isin);
        if (!gotfirst && m) { first = base + __ffs(m) - 1; gotfirst = true; }
        int pos = cnt + __popc(m & ((1u << lane) - 1u));
        if (isin && pos < NSAMP) grp[pos] = i;
        cnt += __popc(m);
    }
    if (cnt < NSAMP) {
        int p0 = cnt + lane;
        if (p0 < NSAMP) grp[p0] = first;
    }
}

// ===================== fused gather + MLP(3) + maxpool =====================
// R5 structure + float2 PAIR LOADS (scalar FFMA chain unchanged, ascending-c
// order -> bit-identical). S0=70 / S1=66 keep LDS.64 conflict-free.
__global__ __launch_bounds__(128) void mlp_kernel(const float* __restrict__ xyz,
                                                  const float* __restrict__ pts,
                                                  float* __restrict__ out)
{
    __shared__ __align__(16) float sW0[O0 * S0];     // 4480 floats
    __shared__ __align__(16) float sW1[O1 * S1];     // 4224
    __shared__ float sb[256 + O2];     // [0,64)=b0 [64,128)=b1 [128,256)=b2
    __shared__ __align__(16) float hin[NSAMP * SH];  // 2176 ; reused as gmax[8][SG]
    __shared__ int   sidx[NSAMP];
    __shared__ float scen[3];

    int t = threadIdx.x;
    int kt = t >> 4;   // 0..7  (k = kt + 8*i)
    int ot = t & 15;   // 0..15

    for (int e = t; e < O0 * C0; e += 128) {
        int o = e / C0, c = e - o * C0;
        sW0[o * S0 + c] = g_W0f[e];
    }
    for (int e = t; e < O1 * O0; e += 128) sW1[(e >> 6) * S1 + (e & 63)] = g_W1f[e];
    if (t < 64)       sb[t] = g_b0f[t];
    else              sb[t] = g_b1f[t - 64];
    for (int e = t; e < O2; e += 128) sb[128 + e] = g_b2f[e];
    __syncthreads();

    for (int g = 0; g < GPB; g++) {
        int gw = blockIdx.x * GPB + g;
        int b = gw >> 10;
        const float* pxyz = xyz + (size_t)b * NN * 3;
        const float* ppts = pts + (size_t)b * NN * ND;

        if (t < NSAMP) sidx[t] = g_grp[(size_t)gw * NSAMP + t];
        if (t < 3)     scen[t] = out[(size_t)gw * 3 + t];
        __syncthreads();

        // gather: hin[k][c] = c<3 ? xyz[id][c]-cen[c] : points[id][c-3]
        for (int e = t; e < NSAMP * C0; e += 128) {
            int k = e / C0;
            int c = e - k * C0;
            int id = sidx[k];
            float v;
            if (c < 3) v = pxyz[3 * id + c] - scen[c];
            else       v = ppts[(size_t)id * ND + (c - 3)];
            hin[k * SH + c] = v;
        }
        __syncthreads();

        // ---- Layer 0: 33 c-pairs + scalar remainder c=66 ----
        {
            float acc[4][4] = {};
            for (int cp = 0; cp < 33; cp++) {
                int c = 2 * cp;
                float2 a2[4], w2[4];
#pragma unroll
                for (int i = 0; i < 4; i++)
                    a2[i] = *reinterpret_cast<const float2*>(&hin[(kt + 8 * i) * SH + c]);
#pragma unroll
                for (int j = 0; j < 4; j++)
                    w2[j] = *reinterpret_cast<const float2*>(&sW0[(ot + 16 * j) * S0 + c]);
#pragma unroll
                for (int i = 0; i < 4; i++)
#pragma unroll
                    for (int j = 0; j < 4; j++) {
                        acc[i][j] = fmaf(a2[i].x, w2[j].x, acc[i][j]);
                        acc[i][j] = fmaf(a2[i].y, w2[j].y, acc[i][j]);
                    }
            }
            {
                float a[4], w[4];
#pragma unroll
                for (int i = 0; i < 4; i++) a[i] = hin[(kt + 8 * i) * SH + 66];
#pragma unroll
                for (int j = 0; j < 4; j++) w[j] = sW0[(ot + 16 * j) * S0 + 66];
#pragma unroll
                for (int i = 0; i < 4; i++)
#pragma unroll
                    for (int j = 0; j < 4; j++) acc[i][j] = fmaf(a[i], w[j], acc[i][j]);
            }
            __syncthreads();   // all reads of hin done
#pragma unroll
            for (int i = 0; i < 4; i++)
#pragma unroll
                for (int j = 0; j < 4; j++) {
                    int k = kt + 8 * i, o = ot + 16 * j;
                    hin[k * SH + o] = fmaxf(acc[i][j] + sb[o], 0.0f);
                }
        }
        __syncthreads();

        // ---- Layer 1: 32 c-pairs ----
        {
            float acc[4][4] = {};
            for (int cp = 0; cp < 32; cp++) {
                int c = 2 * cp;
                float2 a2[4], w2[4];
#pragma unroll
                for (int i = 0; i < 4; i++)
                    a2[i] = *reinterpret_cast<const float2*>(&hin[(kt + 8 * i) * SH + c]);
#pragma unroll
                for (int j = 0; j < 4; j++)
                    w2[j] = *reinterpret_cast<const float2*>(&sW1[(ot + 16 * j) * S1 + c]);
#pragma unroll
                for (int i = 0; i < 4; i++)
#pragma unroll
                    for (int j = 0; j < 4; j++) {
                        acc[i][j] = fmaf(a2[i].x, w2[j].x, acc[i][j]);
                        acc[i][j] = fmaf(a2[i].y, w2[j].y, acc[i][j]);
                    }
            }
            __syncthreads();
#pragma unroll
            for (int i = 0; i < 4; i++)
#pragma unroll
                for (int j = 0; j < 4; j++) {
                    int k = kt + 8 * i, o = ot + 16 * j;
                    hin[k * SH + o] = fmaxf(acc[i][j] + sb[64 + o], 0.0f);
                }
        }
        __syncthreads();

        // ---- Layer 2: c-pairs, a float2, W2 global float4; then max over k ----
        {
            float acc[4][8] = {};
            const float4* W2v = reinterpret_cast<const float4*>(g_W2t);
            for (int cp = 0; cp < 32; cp++) {
                int c = 2 * cp;
                float2 a2[4];
#pragma unroll
                for (int i = 0; i < 4; i++)
                    a2[i] = *reinterpret_cast<const float2*>(&hin[(kt + 8 * i) * SH + c]);
                float4 wx0 = __ldg(&W2v[c * 32 + ot * 2 + 0]);
                float4 wx1 = __ldg(&W2v[c * 32 + ot * 2 + 1]);
                float4 wy0 = __ldg(&W2v[(c + 1) * 32 + ot * 2 + 0]);
                float4 wy1 = __ldg(&W2v[(c + 1) * 32 + ot * 2 + 1]);
                float wx[8] = {wx0.x, wx0.y, wx0.z, wx0.w, wx1.x, wx1.y, wx1.z, wx1.w};
                float wy[8] = {wy0.x, wy0.y, wy0.z, wy0.w, wy1.x, wy1.y, wy1.z, wy1.w};
#pragma unroll
                for (int i = 0; i < 4; i++)
#pragma unroll
                    for (int j = 0; j < 8; j++) {
                        acc[i][j] = fmaf(a2[i].x, wx[j], acc[i][j]);
                        acc[i][j] = fmaf(a2[i].y, wy[j], acc[i][j]);
                    }
            }
            __syncthreads();   // hin reads done; reuse as gmax[8][SG]
            float* gmax = hin;
#pragma unroll
            for (int j = 0; j < 8; j++) {
                int o = ot * 8 + j;
                float bias = sb[128 + o];
                float pm = fmaxf(acc[0][j] + bias, 0.0f);
#pragma unroll
                for (int i = 1; i < 4; i++)
                    pm = fmaxf(pm, fmaxf(acc[i][j] + bias, 0.0f));
                gmax[kt * SG + o] = pm;
            }
            __syncthreads();
            float mx = gmax[t];
#pragma unroll
            for (int q = 1; q < 8; q++) mx = fmaxf(mx, gmax[q * SG + t]);
            out[OUT_XYZ + (size_t)gw * O2 + t] = mx;
        }
        __syncthreads();   // protect hin/sidx before next group's writes
    }
}

// ===================== launch =====================
extern "C" void kernel_launch(void* const* d_in, const int* in_sizes, int n_in,
                              void* d_out, int out_size)
{
    const float* xyz = (const float*)d_in[0];
    const float* pts = (const float*)d_in[1];
    const float* W0  = (const float*)d_in[2];
    const float* b0  = (const float*)d_in[3];
    const float* g0  = (const float*)d_in[4];
    const float* be0 = (const float*)d_in[5];
    const float* m0  = (const float*)d_in[6];
    const float* v0  = (const float*)d_in[7];
    const float* W1  = (const float*)d_in[8];
    const float* b1  = (const float*)d_in[9];
    const float* g1  = (const float*)d_in[10];
    const float* be1 = (const float*)d_in[11];
    const float* m1  = (const float*)d_in[12];
    const float* v1  = (const float*)d_in[13];
    const float* W2  = (const float*)d_in[14];
    const float* b2  = (const float*)d_in[15];
    const float* g2  = (const float*)d_in[16];
    const float* be2 = (const float*)d_in[17];
    const float* m2  = (const float*)d_in[18];
    const float* v2  = (const float*)d_in[19];
    float* out = (float*)d_out;

    // Kernel launches ONLY — graph-capturable. No dynamic smem, no attribute calls.
    fold_kernel<<<1, 256>>>(W0, b0, g0, be0, m0, v0,
                            W1, b1, g1, be1, m1, v1,
                            W2, b2, g2, be2, m2, v2);
    fps_kernel<<<NB, 512>>>(xyz);
    ballquery_kernel<<<(NB * NPOINT) / 8, 256>>>(xyz, out);
    mlp_kernel<<<(NB * NPOINT) / GPB, 128>>>(xyz, pts, out);
}

// round 16
// speedup vs baseline: 1.4443x; 1.3475x over previous
#include <cuda_runtime.h>
#include <cuda_bf16.h>

#define NB 16
#define NN 4096
#define ND 64
#define NPOINT 1024
#define NSAMP 32
#define C0 67
#define OUT_XYZ (NB*NPOINT*3)

// -------- device scratch (no allocations allowed) --------
__device__ int g_fps[NB * NPOINT];
__device__ int g_grp[NB * NPOINT * NSAMP];
// weight fragments in mma.sync B-frag order: [(kt*NT+nt)*32 + lane] -> uint2
__device__ __align__(16) unsigned g_f0h[2560], g_f0l[2560];  // L0: 5kt x 8nt
__device__ __align__(16) unsigned g_f1h[2048], g_f1l[2048];  // L1: 4kt x 8nt
__device__ __align__(16) unsigned g_f2h[4096], g_f2l[4096];  // L2: 4kt x 16nt
__device__ float g_b0f[64], g_b1f[64], g_b2f[128];

// ---- packed f32x2 helpers (FPS distance math — exact rn ops) ----
#define PACK2(out, lo, hi) \
    asm("mov.b64 %0, {%1, %2};" : "=l"(out) : "f"(lo), "f"(hi))
#define UNPACK2(lo, hi, in) \
    asm("mov.b64 {%0, %1}, %2;" : "=f"(lo), "=f"(hi) : "l"(in))
#define ADD2(out, a, b) \
    asm("add.rn.f32x2 %0, %1, %2;" : "=l"(out) : "l"(a), "l"(b))
#define MUL2(out, a, b) \
    asm("mul.rn.f32x2 %0, %1, %2;" : "=l"(out) : "l"(a), "l"(b))
#define FMA2(out, a, b, c) \
    asm("fma.rn.f32x2 %0, %1, %2, %3;" : "=l"(out) : "l"(a), "l"(b), "l"(c))

__device__ __forceinline__ void bf16split(float v, unsigned short& h, unsigned short& l) {
    __nv_bfloat16 hb = __float2bfloat16(v);
    float r = v - __bfloat162float(hb);
    __nv_bfloat16 lb = __float2bfloat16(r);
    h = __bfloat16_as_ushort(hb);
    l = __bfloat16_as_ushort(lb);
}

// mma.sync m16n8k16 bf16 (plain PTX, sm_80+; compiles under compute_103)
__device__ __forceinline__ void do_mma(float* d, const unsigned* a,
                                       unsigned b0, unsigned b1) {
    asm volatile(
        "mma.sync.aligned.m16n8k16.row.col.f32.bf16.bf16.f32 "
        "{%0,%1,%2,%3},{%4,%5,%6,%7},{%8,%9},{%0,%1,%2,%3};"
        : "+f"(d[0]), "+f"(d[1]), "+f"(d[2]), "+f"(d[3])
        : "r"(a[0]), "r"(a[1]), "r"(a[2]), "r"(a[3]), "r"(b0), "r"(b1));
}

// ===================== BN fold -> fragment-ordered bf16 weights ==============
__global__ void fold_kernel(
    const float* __restrict__ W0, const float* __restrict__ b0, const float* __restrict__ g0,
    const float* __restrict__ be0, const float* __restrict__ m0, const float* __restrict__ v0,
    const float* __restrict__ W1, const float* __restrict__ b1, const float* __restrict__ g1,
    const float* __restrict__ be1, const float* __restrict__ m1, const float* __restrict__ v1,
    const float* __restrict__ W2, const float* __restrict__ b2, const float* __restrict__ g2,
    const float* __restrict__ be2, const float* __restrict__ m2, const float* __restrict__ v2)
{
    int t = threadIdx.x;
    int nt = blockDim.x;
    // B frag (col-major): lane holds reg r: elements k = (lane&3)*2 + r*8 + {0,1}, n = lane>>2
    for (int e = t; e < 2560; e += nt) {
        int rr = e & 1, ln = (e >> 1) & 31, nti = (e >> 6) & 7, kt = e >> 9;
        int n = nti * 8 + (ln >> 2);
        int k0 = kt * 16 + (ln & 3) * 2 + rr * 8;
        float s = g0[n] * rsqrtf(v0[n] + 1e-5f);
        float va = (k0 < C0) ? W0[n * C0 + k0] * s : 0.0f;
        float vb = (k0 + 1 < C0) ? W0[n * C0 + k0 + 1] * s : 0.0f;
        unsigned short ha, la, hb, lb;
        bf16split(va, ha, la);
        bf16split(vb, hb, lb);
        g_f0h[e] = ((unsigned)hb << 16) | ha;
        g_f0l[e] = ((unsigned)lb << 16) | la;
    }
    for (int e = t; e < 2048; e += nt) {
        int rr = e & 1, ln = (e >> 1) & 31, nti = (e >> 6) & 7, kt = e >> 9;
        int n = nti * 8 + (ln >> 2);
        int k0 = kt * 16 + (ln & 3) * 2 + rr * 8;
        float s = g1[n] * rsqrtf(v1[n] + 1e-5f);
        unsigned short ha, la, hb, lb;
        bf16split(W1[n * 64 + k0] * s, ha, la);
        bf16split(W1[n * 64 + k0 + 1] * s, hb, lb);
        g_f1h[e] = ((unsigned)hb << 16) | ha;
        g_f1l[e] = ((unsigned)lb << 16) | la;
    }
    for (int e = t; e < 4096; e += nt) {
        int rr = e & 1, ln = (e >> 1) & 31, nti = (e >> 6) & 15, kt = e >> 10;
        int n = nti * 8 + (ln >> 2);
        int k0 = kt * 16 + (ln & 3) * 2 + rr * 8;
        float s = g2[n] * rsqrtf(v2[n] + 1e-5f);
        unsigned short ha, la, hb, lb;
        bf16split(W2[n * 64 + k0] * s, ha, la);
        bf16split(W2[n * 64 + k0 + 1] * s, hb, lb);
        g_f2h[e] = ((unsigned)hb << 16) | ha;
        g_f2l[e] = ((unsigned)lb << 16) | la;
    }
    for (int o = t; o < 64; o += nt)
        g_b0f[o] = (b0[o] - m0[o]) * (g0[o] * rsqrtf(v0[o] + 1e-5f)) + be0[o];
    for (int o = t; o < 64; o += nt)
        g_b1f[o] = (b1[o] - m1[o]) * (g1[o] * rsqrtf(v1[o] + 1e-5f)) + be1[o];
    for (int o = t; o < 128; o += nt)
        g_b2f[o] = (b2[o] - m2[o]) * (g2[o] * rsqrtf(v2[o] + 1e-5f)) + be2[o];
}

// ===================== FPS (R12-R14 version — selections bit-exact) ==========
__global__ __launch_bounds__(512) void fps_kernel(const float* __restrict__ xyz)
{
    __shared__ unsigned swv[2][16];
    __shared__ unsigned swi[2][16];

    int b = blockIdx.x;
    int t = threadIdx.x;
    int w = t >> 5;
    int lane = t & 31;
    const float* p = xyz + (size_t)b * NN * 3;

    float dl[8];
    unsigned long long px2[4], py2[4], pz2[4];
#pragma unroll
    for (int j = 0; j < 4; j++) {
        int p0 = t + (2 * j) * 512;
        int p1 = t + (2 * j + 1) * 512;
        float x0 = p[3 * p0], y0 = p[3 * p0 + 1], z0 = p[3 * p0 + 2];
        float x1 = p[3 * p1], y1 = p[3 * p1 + 1], z1 = p[3 * p1 + 2];
        PACK2(px2[j], x0, x1);
        PACK2(py2[j], y0, y1);
        PACK2(pz2[j], z0, z1);
        dl[2 * j] = 1e10f;
        dl[2 * j + 1] = 1e10f;
    }
    if (t == 0) g_fps[b * NPOINT] = 0;

    float cx = p[0], cy = p[1], cz = p[2];
    for (int it = 1; it < NPOINT; it++) {
        unsigned long long ncx2, ncy2, ncz2;
        {
            float nx = -cx, ny = -cy, nz = -cz;
            PACK2(ncx2, nx, nx);
            PACK2(ncy2, ny, ny);
            PACK2(ncz2, nz, nz);
        }
        float bv = -1.0f;
#pragma unroll
        for (int j = 0; j < 4; j++) {
            unsigned long long dxp, dyp, dzp, dp;
            ADD2(dxp, px2[j], ncx2);
            ADD2(dyp, py2[j], ncy2);
            ADD2(dzp, pz2[j], ncz2);
            MUL2(dp, dxp, dxp);
            FMA2(dp, dyp, dyp, dp);
            FMA2(dp, dzp, dzp, dp);
            float d0, d1;
            UNPACK2(d0, d1, dp);
            float dn0 = fminf(dl[2 * j], d0);
            dl[2 * j] = dn0;
            bv = fmaxf(bv, dn0);
            float dn1 = fminf(dl[2 * j + 1], d1);
            dl[2 * j + 1] = dn1;
            bv = fmaxf(bv, dn1);
        }
        int bi = t + 7 * 512;
#pragma unroll
        for (int i = 6; i >= 0; i--)
            bi = (dl[i] == bv) ? (t + i * 512) : bi;
        unsigned vb = __float_as_uint(bv);
        unsigned wmax = __reduce_max_sync(0xffffffffu, vb);
        unsigned cand = (vb == wmax) ? (unsigned)bi : 0xffffffffu;
        unsigned widx = __reduce_min_sync(0xffffffffu, cand);
        int par = it & 1;
        if (lane == 0) {
            swv[par][w] = wmax;
            swi[par][w] = widx;
        }
        __syncthreads();
        unsigned sv = swv[par][lane & 15];
        unsigned gmax = __reduce_max_sync(0xffffffffu, sv);
        unsigned c2 = (sv == gmax) ? swi[par][lane & 15] : 0xffffffffu;
        unsigned idx = __reduce_min_sync(0xffffffffu, c2);
        cx = p[3 * idx]; cy = p[3 * idx + 1]; cz = p[3 * idx + 2];
        if (t == 0) g_fps[b * NPOINT + it] = (int)idx;
    }
}

// ===================== ball query (+new_xyz write) =====================
__global__ __launch_bounds__(256) void ballquery_kernel(const float* __restrict__ xyz,
                                                        float* __restrict__ out)
{
    int gw = (blockIdx.x * 256 + threadIdx.x) >> 5;
    int lane = threadIdx.x & 31;
    if (gw >= NB * NPOINT) return;
    int b = gw >> 10;
    const float* p = xyz + (size_t)b * NN * 3;

    int ci = g_fps[gw];
    float cx = p[3 * ci + 0];
    float cy = p[3 * ci + 1];
    float cz = p[3 * ci + 2];
    if (lane < 3) out[(size_t)gw * 3 + lane] = p[3 * ci + lane];

    float sn = fmaf(cz, cz, fmaf(cy, cy, __fmul_rn(cx, cx)));
    int* grp = g_grp + (size_t)gw * NSAMP;

    int cnt = 0;
    int first = ci;
    bool gotfirst = false;
    for (int base = 0; base < NN && cnt < NSAMP; base += 32) {
        int i = base + lane;
        float x = p[3 * i + 0], y = p[3 * i + 1], z = p[3 * i + 2];
        float sp = fmaf(z, z, fmaf(y, y, __fmul_rn(x, x)));
        float dt = fmaf(cz, z, fmaf(cy, y, __fmul_rn(cx, x)));
        float d2 = fmaf(-2.0f, dt, sn + sp);
        bool isin = !(d2 > 0.04f);
        unsigned m = __ballot_sync(0xffffffffu, isin);
        if (!gotfirst && m) { first = base + __ffs(m) - 1; gotfirst = true; }
        int pos = cnt + __popc(m & ((1u << lane) - 1u));
        if (isin && pos < NSAMP) grp[pos] = i;
        cnt += __popc(m);
    }
    if (cnt < NSAMP) {
        int p0 = cnt + lane;
        if (p0 < NSAMP) grp[p0] = first;
    }
}

// ===================== HMMA MLP: warp = one group (M=32) =====================
// A hi/lo planes per warp in smem [32 rows x 41 u32]; W frags per-lane LDG.64
// from L1-resident global; 3 compensated passes accumulate in fp32 HMMA acc.
#define AST 41
__device__ __forceinline__ void run_gemm(const unsigned* Ah, const unsigned* Al,
                                         const unsigned* fh, const unsigned* fl,
                                         int KT, int NTT, int ntbase, int lane,
                                         float acc[2][8][4])
{
#pragma unroll
    for (int pass = 0; pass < 3; pass++) {
        const unsigned* Ap = (pass == 1) ? Al : Ah;
        const uint2* Wp = reinterpret_cast<const uint2*>((pass == 2) ? fl : fh);
        for (int kt = 0; kt < KT; kt++) {
            int r = lane >> 2, cq = (lane & 3) + kt * 8;
            unsigned af0[4], af1[4];
            af0[0] = Ap[r * AST + cq];
            af0[1] = Ap[(r + 8) * AST + cq];
            af0[2] = Ap[r * AST + cq + 4];
            af0[3] = Ap[(r + 8) * AST + cq + 4];
            af1[0] = Ap[(r + 16) * AST + cq];
            af1[1] = Ap[(r + 24) * AST + cq];
            af1[2] = Ap[(r + 16) * AST + cq + 4];
            af1[3] = Ap[(r + 24) * AST + cq + 4];
#pragma unroll
            for (int nt = 0; nt < 8; nt++) {
                uint2 wv = __ldg(&Wp[(kt * NTT + ntbase + nt) * 32 + lane]);
                do_mma(acc[0][nt], af0, wv.x, wv.y);
                do_mma(acc[1][nt], af1, wv.x, wv.y);
            }
        }
    }
}

__global__ __launch_bounds__(128, 4) void mlp_kernel(const float* __restrict__ xyz,
                                                     const float* __restrict__ pts,
                                                     float* __restrict__ out)
{
    __shared__ unsigned As[4][2][32 * AST];   // [warp][plane] 41.98KB
    __shared__ float sb[256];

    int t = threadIdx.x;
    int w = t >> 5;
    int lane = t & 31;

    if (t < 64) sb[t] = g_b0f[t];
    else        sb[t] = g_b1f[t - 64];
    for (int e = t; e < 128; e += 128) sb[128 + e] = g_b2f[e];
    __syncthreads();

    int gw = blockIdx.x * 4 + w;
    int bb = gw >> 10;
    const float* pxyz = xyz + (size_t)bb * NN * 3;
    const float* ppts = pts + (size_t)bb * NN * ND;
    unsigned* Ah = As[w][0];
    unsigned* Al = As[w][1];

    // ---- gather: lane = sample row; 40 u32 col-pairs (c, c+1), pad to 80 ----
    {
        int id = g_grp[(size_t)gw * NSAMP + lane];
        float cen0 = out[(size_t)gw * 3 + 0];
        float cen1 = out[(size_t)gw * 3 + 1];
        float cen2 = out[(size_t)gw * 3 + 2];
#pragma unroll
        for (int cp = 0; cp < 40; cp++) {
            int c0 = 2 * cp, c1 = 2 * cp + 1;
            float v0, v1;
            if (c0 == 0)      v0 = pxyz[3 * id + 0] - cen0;
            else if (c0 == 2) v0 = pxyz[3 * id + 2] - cen2;
            else              v0 = (c0 < C0) ? ppts[(size_t)id * ND + (c0 - 3)] : 0.0f;
            if (c1 == 1)      v1 = pxyz[3 * id + 1] - cen1;
            else              v1 = (c1 < C0) ? ppts[(size_t)id * ND + (c1 - 3)] : 0.0f;
            unsigned short h0, l0, h1, l1;
            bf16split(v0, h0, l0);
            bf16split(v1, h1, l1);
            Ah[lane * AST + cp] = ((unsigned)h1 << 16) | h0;
            Al[lane * AST + cp] = ((unsigned)l1 << 16) | l0;
        }
    }
    __syncwarp();

    // ---- Layer 0 (KT=5) and Layer 1 (KT=4): GEMM + bias/ReLU/resplit ----
#pragma unroll
    for (int layer = 0; layer < 2; layer++) {
        float acc[2][8][4] = {};
        if (layer == 0) run_gemm(Ah, Al, g_f0h, g_f0l, 5, 8, 0, lane, acc);
        else            run_gemm(Ah, Al, g_f1h, g_f1l, 4, 8, 0, lane, acc);
        __syncwarp();   // all frag reads done before in-place writes
        int boff = layer * 64;
#pragma unroll
        for (int nt = 0; nt < 8; nt++) {
            int o0 = nt * 8 + (lane & 3) * 2;
            float bv0 = sb[boff + o0], bv1 = sb[boff + o0 + 1];
            int col = (lane & 3) + nt * 4;
#pragma unroll
            for (int mt = 0; mt < 2; mt++) {
                int r = (lane >> 2) + mt * 16;
                float v00 = fmaxf(acc[mt][nt][0] + bv0, 0.0f);
                float v01 = fmaxf(acc[mt][nt][1] + bv1, 0.0f);
                float v10 = fmaxf(acc[mt][nt][2] + bv0, 0.0f);
                float v11 = fmaxf(acc[mt][nt][3] + bv1, 0.0f);
                unsigned short h0, l0, h1, l1;
                bf16split(v00, h0, l0);
                bf16split(v01, h1, l1);
                Ah[r * AST + col] = ((unsigned)h1 << 16) | h0;
                Al[r * AST + col] = ((unsigned)l1 << 16) | l0;
                bf16split(v10, h0, l0);
                bf16split(v11, h1, l1);
                Ah[(r + 8) * AST + col] = ((unsigned)h1 << 16) | h0;
                Al[(r + 8) * AST + col] = ((unsigned)l1 << 16) | l0;
            }
        }
        __syncwarp();
    }

    // ---- Layer 2: two N=64 halves, maxpool straight out of acc ----
#pragma unroll
    for (int h = 0; h < 2; h++) {
        float acc[2][8][4] = {};
        run_gemm(Ah, Al, g_f2h, g_f2l, 4, 16, h * 8, lane, acc);
#pragma unroll
        for (int nt = 0; nt < 8; nt++) {
            int o0 = h * 64 + nt * 8 + (lane & 3) * 2;
            float bv0 = sb[128 + o0], bv1 = sb[128 + o0 + 1];
            float ve = fmaxf(fmaxf(acc[0][nt][0] + bv0, 0.0f),
                             fmaxf(acc[0][nt][2] + bv0, 0.0f));
            ve = fmaxf(ve, fmaxf(fmaxf(acc[1][nt][0] + bv0, 0.0f),
                                 fmaxf(acc[1][nt][2] + bv0, 0.0f)));
            float vo = fmaxf(fmaxf(acc[0][nt][1] + bv1, 0.0f),
                             fmaxf(acc[0][nt][3] + bv1, 0.0f));
            vo = fmaxf(vo, fmaxf(fmaxf(acc[1][nt][1] + bv1, 0.0f),
                                 fmaxf(acc[1][nt][3] + bv1, 0.0f)));
#pragma unroll
            for (int off = 4; off < 32; off <<= 1) {
                ve = fmaxf(ve, __shfl_xor_sync(0xffffffffu, ve, off));
                vo = fmaxf(vo, __shfl_xor_sync(0xffffffffu, vo, off));
            }
            if (lane < 4) {
                out[OUT_XYZ + (size_t)gw * 128 + o0] = ve;
                out[OUT_XYZ + (size_t)gw * 128 + o0 + 1] = vo;
            }
        }
    }
}

// ===================== launch =====================
extern "C" void kernel_launch(void* const* d_in, const int* in_sizes, int n_in,
                              void* d_out, int out_size)
{
    const float* xyz = (const float*)d_in[0];
    const float* pts = (const float*)d_in[1];
    const float* W0  = (const float*)d_in[2];
    const float* b0  = (const float*)d_in[3];
    const float* g0  = (const float*)d_in[4];
    const float* be0 = (const float*)d_in[5];
    const float* m0  = (const float*)d_in[6];
    const float* v0  = (const float*)d_in[7];
    const float* W1  = (const float*)d_in[8];
    const float* b1  = (const float*)d_in[9];
    const float* g1  = (const float*)d_in[10];
    const float* be1 = (const float*)d_in[11];
    const float* m1  = (const float*)d_in[12];
    const float* v1  = (const float*)d_in[13];
    const float* W2  = (const float*)d_in[14];
    const float* b2  = (const float*)d_in[15];
    const float* g2  = (const float*)d_in[16];
    const float* be2 = (const float*)d_in[17];
    const float* m2  = (const float*)d_in[18];
    const float* v2  = (const float*)d_in[19];
    float* out = (float*)d_out;

    // Kernel launches ONLY — graph-capturable. No dynamic smem, no attribute calls.
    fold_kernel<<<1, 256>>>(W0, b0, g0, be0, m0, v0,
                            W1, b1, g1, be1, m1, v1,
                            W2, b2, g2, be2, m2, v2);
    fps_kernel<<<NB, 512>>>(xyz);
    ballquery_kernel<<<(NB * NPOINT) / 8, 256>>>(xyz, out);
    mlp_kernel<<<(NB * NPOINT) / 4, 128>>>(xyz, pts, out);
}

// round 17
// speedup vs baseline: 1.5856x; 1.0978x over previous
#include <cuda_runtime.h>
#include <cuda_bf16.h>

#define NB 16
#define NN 4096
#define ND 64
#define NPOINT 1024
#define NSAMP 32
#define C0 67
#define OUT_XYZ (NB*NPOINT*3)

// -------- device scratch (no allocations allowed) --------
__device__ int g_fps[NB * NPOINT];
__device__ int g_grp[NB * NPOINT * NSAMP];
// weight fragments in mma.sync B-frag order: [(kt*NT+nt)*32 + lane] -> uint2
__device__ __align__(16) unsigned g_f0h[2560], g_f0l[2560];  // L0: 5kt x 8nt
__device__ __align__(16) unsigned g_f1h[2048], g_f1l[2048];  // L1: 4kt x 8nt
__device__ __align__(16) unsigned g_f2h[4096], g_f2l[4096];  // L2: 4kt x 16nt
__device__ float g_b0f[64], g_b1f[64], g_b2f[128];

// ---- packed f32x2 helpers (FPS distance math — exact rn ops) ----
#define PACK2(out, lo, hi) \
    asm("mov.b64 %0, {%1, %2};" : "=l"(out) : "f"(lo), "f"(hi))
#define UNPACK2(lo, hi, in) \
    asm("mov.b64 {%0, %1}, %2;" : "=f"(lo), "=f"(hi) : "l"(in))
#define ADD2(out, a, b) \
    asm("add.rn.f32x2 %0, %1, %2;" : "=l"(out) : "l"(a), "l"(b))
#define MUL2(out, a, b) \
    asm("mul.rn.f32x2 %0, %1, %2;" : "=l"(out) : "l"(a), "l"(b))
#define FMA2(out, a, b, c) \
    asm("fma.rn.f32x2 %0, %1, %2, %3;" : "=l"(out) : "l"(a), "l"(b), "l"(c))

__device__ __forceinline__ void bf16split(float v, unsigned short& h, unsigned short& l) {
    __nv_bfloat16 hb = __float2bfloat16(v);
    float r = v - __bfloat162float(hb);
    __nv_bfloat16 lb = __float2bfloat16(r);
    h = __bfloat16_as_ushort(hb);
    l = __bfloat16_as_ushort(lb);
}

// mma.sync m16n8k16 bf16 (plain PTX, sm_80+; compiles under compute_103)
__device__ __forceinline__ void do_mma(float* d, const unsigned* a,
                                       unsigned b0, unsigned b1) {
    asm volatile(
        "mma.sync.aligned.m16n8k16.row.col.f32.bf16.bf16.f32 "
        "{%0,%1,%2,%3},{%4,%5,%6,%7},{%8,%9},{%0,%1,%2,%3};"
        : "+f"(d[0]), "+f"(d[1]), "+f"(d[2]), "+f"(d[3])
        : "r"(a[0]), "r"(a[1]), "r"(a[2]), "r"(a[3]), "r"(b0), "r"(b1));
}

// ===================== BN fold -> fragment-ordered bf16 weights ==============
__global__ void fold_kernel(
    const float* __restrict__ W0, const float* __restrict__ b0, const float* __restrict__ g0,
    const float* __restrict__ be0, const float* __restrict__ m0, const float* __restrict__ v0,
    const float* __restrict__ W1, const float* __restrict__ b1, const float* __restrict__ g1,
    const float* __restrict__ be1, const float* __restrict__ m1, const float* __restrict__ v1,
    const float* __restrict__ W2, const float* __restrict__ b2, const float* __restrict__ g2,
    const float* __restrict__ be2, const float* __restrict__ m2, const float* __restrict__ v2)
{
    int t = threadIdx.x;
    int nt = blockDim.x;
    // B frag (col-major): lane holds reg r: elements k = (lane&3)*2 + r*8 + {0,1}, n = lane>>2
    for (int e = t; e < 2560; e += nt) {
        int rr = e & 1, ln = (e >> 1) & 31, nti = (e >> 6) & 7, kt = e >> 9;
        int n = nti * 8 + (ln >> 2);
        int k0 = kt * 16 + (ln & 3) * 2 + rr * 8;
        float s = g0[n] * rsqrtf(v0[n] + 1e-5f);
        float va = (k0 < C0) ? W0[n * C0 + k0] * s : 0.0f;
        float vb = (k0 + 1 < C0) ? W0[n * C0 + k0 + 1] * s : 0.0f;
        unsigned short ha, la, hb, lb;
        bf16split(va, ha, la);
        bf16split(vb, hb, lb);
        g_f0h[e] = ((unsigned)hb << 16) | ha;
        g_f0l[e] = ((unsigned)lb << 16) | la;
    }
    for (int e = t; e < 2048; e += nt) {
        int rr = e & 1, ln = (e >> 1) & 31, nti = (e >> 6) & 7, kt = e >> 9;
        int n = nti * 8 + (ln >> 2);
        int k0 = kt * 16 + (ln & 3) * 2 + rr * 8;
        float s = g1[n] * rsqrtf(v1[n] + 1e-5f);
        unsigned short ha, la, hb, lb;
        bf16split(W1[n * 64 + k0] * s, ha, la);
        bf16split(W1[n * 64 + k0 + 1] * s, hb, lb);
        g_f1h[e] = ((unsigned)hb << 16) | ha;
        g_f1l[e] = ((unsigned)lb << 16) | la;
    }
    for (int e = t; e < 4096; e += nt) {
        int rr = e & 1, ln = (e >> 1) & 31, nti = (e >> 6) & 15, kt = e >> 10;
        int n = nti * 8 + (ln >> 2);
        int k0 = kt * 16 + (ln & 3) * 2 + rr * 8;
        float s = g2[n] * rsqrtf(v2[n] + 1e-5f);
        unsigned short ha, la, hb, lb;
        bf16split(W2[n * 64 + k0] * s, ha, la);
        bf16split(W2[n * 64 + k0 + 1] * s, hb, lb);
        g_f2h[e] = ((unsigned)hb << 16) | ha;
        g_f2l[e] = ((unsigned)lb << 16) | la;
    }
    for (int o = t; o < 64; o += nt)
        g_b0f[o] = (b0[o] - m0[o]) * (g0[o] * rsqrtf(v0[o] + 1e-5f)) + be0[o];
    for (int o = t; o < 64; o += nt)
        g_b1f[o] = (b1[o] - m1[o]) * (g1[o] * rsqrtf(v1[o] + 1e-5f)) + be1[o];
    for (int o = t; o < 128; o += nt)
        g_b2f[o] = (b2[o] - m2[o]) * (g2[o] * rsqrtf(v2[o] + 1e-5f)) + be2[o];
}

// ===================== FPS (R12-R14 version — selections bit-exact) ==========
__global__ __launch_bounds__(512) void fps_kernel(const float* __restrict__ xyz)
{
    __shared__ unsigned swv[2][16];
    __shared__ unsigned swi[2][16];

    int b = blockIdx.x;
    int t = threadIdx.x;
    int w = t >> 5;
    int lane = t & 31;
    const float* p = xyz + (size_t)b * NN * 3;

    float dl[8];
    unsigned long long px2[4], py2[4], pz2[4];
#pragma unroll
    for (int j = 0; j < 4; j++) {
        int p0 = t + (2 * j) * 512;
        int p1 = t + (2 * j + 1) * 512;
        float x0 = p[3 * p0], y0 = p[3 * p0 + 1], z0 = p[3 * p0 + 2];
        float x1 = p[3 * p1], y1 = p[3 * p1 + 1], z1 = p[3 * p1 + 2];
        PACK2(px2[j], x0, x1);
        PACK2(py2[j], y0, y1);
        PACK2(pz2[j], z0, z1);
        dl[2 * j] = 1e10f;
        dl[2 * j + 1] = 1e10f;
    }
    if (t == 0) g_fps[b * NPOINT] = 0;

    float cx = p[0], cy = p[1], cz = p[2];
    for (int it = 1; it < NPOINT; it++) {
        unsigned long long ncx2, ncy2, ncz2;
        {
            float nx = -cx, ny = -cy, nz = -cz;
            PACK2(ncx2, nx, nx);
            PACK2(ncy2, ny, ny);
            PACK2(ncz2, nz, nz);
        }
        float bv = -1.0f;
#pragma unroll
        for (int j = 0; j < 4; j++) {
            unsigned long long dxp, dyp, dzp, dp;
            ADD2(dxp, px2[j], ncx2);
            ADD2(dyp, py2[j], ncy2);
            ADD2(dzp, pz2[j], ncz2);
            MUL2(dp, dxp, dxp);
            FMA2(dp, dyp, dyp, dp);
            FMA2(dp, dzp, dzp, dp);
            float d0, d1;
            UNPACK2(d0, d1, dp);
            float dn0 = fminf(dl[2 * j], d0);
            dl[2 * j] = dn0;
            bv = fmaxf(bv, dn0);
            float dn1 = fminf(dl[2 * j + 1], d1);
            dl[2 * j + 1] = dn1;
            bv = fmaxf(bv, dn1);
        }
        int bi = t + 7 * 512;
#pragma unroll
        for (int i = 6; i >= 0; i--)
            bi = (dl[i] == bv) ? (t + i * 512) : bi;
        unsigned vb = __float_as_uint(bv);
        unsigned wmax = __reduce_max_sync(0xffffffffu, vb);
        unsigned cand = (vb == wmax) ? (unsigned)bi : 0xffffffffu;
        unsigned widx = __reduce_min_sync(0xffffffffu, cand);
        int par = it & 1;
        if (lane == 0) {
            swv[par][w] = wmax;
            swi[par][w] = widx;
        }
        __syncthreads();
        unsigned sv = swv[par][lane & 15];
        unsigned gmax = __reduce_max_sync(0xffffffffu, sv);
        unsigned c2 = (sv == gmax) ? swi[par][lane & 15] : 0xffffffffu;
        unsigned idx = __reduce_min_sync(0xffffffffu, c2);
        cx = p[3 * idx]; cy = p[3 * idx + 1]; cz = p[3 * idx + 2];
        if (t == 0) g_fps[b * NPOINT + it] = (int)idx;
    }
}

// ===================== ball query (+new_xyz write) =====================
__global__ __launch_bounds__(256) void ballquery_kernel(const float* __restrict__ xyz,
                                                        float* __restrict__ out)
{
    int gw = (blockIdx.x * 256 + threadIdx.x) >> 5;
    int lane = threadIdx.x & 31;
    if (gw >= NB * NPOINT) return;
    int b = gw >> 10;
    const float* p = xyz + (size_t)b * NN * 3;

    int ci = g_fps[gw];
    float cx = p[3 * ci + 0];
    float cy = p[3 * ci + 1];
    float cz = p[3 * ci + 2];
    if (lane < 3) out[(size_t)gw * 3 + lane] = p[3 * ci + lane];

    float sn = fmaf(cz, cz, fmaf(cy, cy, __fmul_rn(cx, cx)));
    int* grp = g_grp + (size_t)gw * NSAMP;

    int cnt = 0;
    int first = ci;
    bool gotfirst = false;
    for (int base = 0; base < NN && cnt < NSAMP; base += 32) {
        int i = base + lane;
        float x = p[3 * i + 0], y = p[3 * i + 1], z = p[3 * i + 2];
        float sp = fmaf(z, z, fmaf(y, y, __fmul_rn(x, x)));
        float dt = fmaf(cz, z, fmaf(cy, y, __fmul_rn(cx, x)));
        float d2 = fmaf(-2.0f, dt, sn + sp);
        bool isin = !(d2 > 0.04f);
        unsigned m = __ballot_sync(0xffffffffu, isin);
        if (!gotfirst && m) { first = base + __ffs(m) - 1; gotfirst = true; }
        int pos = cnt + __popc(m & ((1u << lane) - 1u));
        if (isin && pos < NSAMP) grp[pos] = i;
        cnt += __popc(m);
    }
    if (cnt < NSAMP) {
        int p0 = cnt + lane;
        if (p0 < NSAMP) grp[p0] = first;
    }
}

// ===================== HMMA MLP: warp = one group (M=32) =====================
// FUSED compensation: per kt load Ah+Al frags once, per (kt,nt) load Wh+Wl
// once; all three products (AhWh + AlWh + AhWl) accumulate into one fp32 acc.
// L1 traffic ~0.67x of the 3-pass version; mma count unchanged.
#define AST 41
__device__ __forceinline__ void run_gemm(const unsigned* Ah, const unsigned* Al,
                                         const unsigned* fh, const unsigned* fl,
                                         int KT, int NTT, int ntbase, int lane,
                                         float acc[2][8][4])
{
    const uint2* Wh = reinterpret_cast<const uint2*>(fh);
    const uint2* Wl = reinterpret_cast<const uint2*>(fl);
    for (int kt = 0; kt < KT; kt++) {
        int r = lane >> 2, cq = (lane & 3) + kt * 8;
        unsigned ah0[4], ah1[4], al0[4], al1[4];
        ah0[0] = Ah[r * AST + cq];
        ah0[1] = Ah[(r + 8) * AST + cq];
        ah0[2] = Ah[r * AST + cq + 4];
        ah0[3] = Ah[(r + 8) * AST + cq + 4];
        ah1[0] = Ah[(r + 16) * AST + cq];
        ah1[1] = Ah[(r + 24) * AST + cq];
        ah1[2] = Ah[(r + 16) * AST + cq + 4];
        ah1[3] = Ah[(r + 24) * AST + cq + 4];
        al0[0] = Al[r * AST + cq];
        al0[1] = Al[(r + 8) * AST + cq];
        al0[2] = Al[r * AST + cq + 4];
        al0[3] = Al[(r + 8) * AST + cq + 4];
        al1[0] = Al[(r + 16) * AST + cq];
        al1[1] = Al[(r + 24) * AST + cq];
        al1[2] = Al[(r + 16) * AST + cq + 4];
        al1[3] = Al[(r + 24) * AST + cq + 4];
#pragma unroll
        for (int nt = 0; nt < 8; nt++) {
            uint2 wh = __ldg(&Wh[(kt * NTT + ntbase + nt) * 32 + lane]);
            uint2 wl = __ldg(&Wl[(kt * NTT + ntbase + nt) * 32 + lane]);
            do_mma(acc[0][nt], ah0, wh.x, wh.y);
            do_mma(acc[1][nt], ah1, wh.x, wh.y);
            do_mma(acc[0][nt], al0, wh.x, wh.y);
            do_mma(acc[1][nt], al1, wh.x, wh.y);
            do_mma(acc[0][nt], ah0, wl.x, wl.y);
            do_mma(acc[1][nt], ah1, wl.x, wl.y);
        }
    }
}

__global__ __launch_bounds__(128, 4) void mlp_kernel(const float* __restrict__ xyz,
                                                     const float* __restrict__ pts,
                                                     float* __restrict__ out)
{
    __shared__ unsigned As[4][2][32 * AST];   // [warp][plane] 41.98KB
    __shared__ float sb[256];

    int t = threadIdx.x;
    int w = t >> 5;
    int lane = t & 31;

    if (t < 64) sb[t] = g_b0f[t];
    else        sb[t] = g_b1f[t - 64];
    for (int e = t; e < 128; e += 128) sb[128 + e] = g_b2f[e];
    __syncthreads();

    int gw = blockIdx.x * 4 + w;
    int bb = gw >> 10;
    const float* pxyz = xyz + (size_t)bb * NN * 3;
    const float* ppts = pts + (size_t)bb * NN * ND;
    unsigned* Ah = As[w][0];
    unsigned* Al = As[w][1];

    // ---- gather: lane = sample row; 40 u32 col-pairs (c, c+1), pad to 80 ----
    {
        int id = g_grp[(size_t)gw * NSAMP + lane];
        float cen0 = out[(size_t)gw * 3 + 0];
        float cen1 = out[(size_t)gw * 3 + 1];
        float cen2 = out[(size_t)gw * 3 + 2];
#pragma unroll
        for (int cp = 0; cp < 40; cp++) {
            int c0 = 2 * cp, c1 = 2 * cp + 1;
            float v0, v1;
            if (c0 == 0)      v0 = pxyz[3 * id + 0] - cen0;
            else if (c0 == 2) v0 = pxyz[3 * id + 2] - cen2;
            else              v0 = (c0 < C0) ? ppts[(size_t)id * ND + (c0 - 3)] : 0.0f;
            if (c1 == 1)      v1 = pxyz[3 * id + 1] - cen1;
            else              v1 = (c1 < C0) ? ppts[(size_t)id * ND + (c1 - 3)] : 0.0f;
            unsigned short h0, l0, h1, l1;
            bf16split(v0, h0, l0);
            bf16split(v1, h1, l1);
            Ah[lane * AST + cp] = ((unsigned)h1 << 16) | h0;
            Al[lane * AST + cp] = ((unsigned)l1 << 16) | l0;
        }
    }
    __syncwarp();

    // ---- Layer 0 (KT=5) and Layer 1 (KT=4): GEMM + bias/ReLU/resplit ----
#pragma unroll
    for (int layer = 0; layer < 2; layer++) {
        float acc[2][8][4] = {};
        if (layer == 0) run_gemm(Ah, Al, g_f0h, g_f0l, 5, 8, 0, lane, acc);
        else            run_gemm(Ah, Al, g_f1h, g_f1l, 4, 8, 0, lane, acc);
        __syncwarp();   // all frag reads done before in-place writes
        int boff = layer * 64;
#pragma unroll
        for (int nt = 0; nt < 8; nt++) {
            int o0 = nt * 8 + (lane & 3) * 2;
            float bv0 = sb[boff + o0], bv1 = sb[boff + o0 + 1];
            int col = (lane & 3) + nt * 4;
#pragma unroll
            for (int mt = 0; mt < 2; mt++) {
                int r = (lane >> 2) + mt * 16;
                float v00 = fmaxf(acc[mt][nt][0] + bv0, 0.0f);
                float v01 = fmaxf(acc[mt][nt][1] + bv1, 0.0f);
                float v10 = fmaxf(acc[mt][nt][2] + bv0, 0.0f);
                float v11 = fmaxf(acc[mt][nt][3] + bv1, 0.0f);
                unsigned short h0, l0, h1, l1;
                bf16split(v00, h0, l0);
                bf16split(v01, h1, l1);
                Ah[r * AST + col] = ((unsigned)h1 << 16) | h0;
                Al[r * AST + col] = ((unsigned)l1 << 16) | l0;
                bf16split(v10, h0, l0);
                bf16split(v11, h1, l1);
                Ah[(r + 8) * AST + col] = ((unsigned)h1 << 16) | h0;
                Al[(r + 8) * AST + col] = ((unsigned)l1 << 16) | l0;
            }
        }
        __syncwarp();
    }

    // ---- Layer 2: two N=64 halves, maxpool straight out of acc ----
#pragma unroll
    for (int h = 0; h < 2; h++) {
        float acc[2][8][4] = {};
        run_gemm(Ah, Al, g_f2h, g_f2l, 4, 16, h * 8, lane, acc);
#pragma unroll
        for (int nt = 0; nt < 8; nt++) {
            int o0 = h * 64 + nt * 8 + (lane & 3) * 2;
            float bv0 = sb[128 + o0], bv1 = sb[128 + o0 + 1];
            float ve = fmaxf(fmaxf(acc[0][nt][0] + bv0, 0.0f),
                             fmaxf(acc[0][nt][2] + bv0, 0.0f));
            ve = fmaxf(ve, fmaxf(fmaxf(acc[1][nt][0] + bv0, 0.0f),
                                 fmaxf(acc[1][nt][2] + bv0, 0.0f)));
            float vo = fmaxf(fmaxf(acc[0][nt][1] + bv1, 0.0f),
                             fmaxf(acc[0][nt][3] + bv1, 0.0f));
            vo = fmaxf(vo, fmaxf(fmaxf(acc[1][nt][1] + bv1, 0.0f),
                                 fmaxf(acc[1][nt][3] + bv1, 0.0f)));
#pragma unroll
            for (int off = 4; off < 32; off <<= 1) {
                ve = fmaxf(ve, __shfl_xor_sync(0xffffffffu, ve, off));
                vo = fmaxf(vo, __shfl_xor_sync(0xffffffffu, vo, off));
            }
            if (lane < 4) {
                out[OUT_XYZ + (size_t)gw * 128 + o0] = ve;
                out[OUT_XYZ + (size_t)gw * 128 + o0 + 1] = vo;
            }
        }
    }
}

// ===================== launch =====================
extern "C" void kernel_launch(void* const* d_in, const int* in_sizes, int n_in,
                              void* d_out, int out_size)
{
    const float* xyz = (const float*)d_in[0];
    const float* pts = (const float*)d_in[1];
    const float* W0  = (const float*)d_in[2];
    const float* b0  = (const float*)d_in[3];
    const float* g0  = (const float*)d_in[4];
    const float* be0 = (const float*)d_in[5];
    const float* m0  = (const float*)d_in[6];
    const float* v0  = (const float*)d_in[7];
    const float* W1  = (const float*)d_in[8];
    const float* b1  = (const float*)d_in[9];
    const float* g1  = (const float*)d_in[10];
    const float* be1 = (const float*)d_in[11];
    const float* m1  = (const float*)d_in[12];
    const float* v1  = (const float*)d_in[13];
    const float* W2  = (const float*)d_in[14];
    const float* b2  = (const float*)d_in[15];
    const float* g2  = (const float*)d_in[16];
    const float* be2 = (const float*)d_in[17];
    const float* m2  = (const float*)d_in[18];
    const float* v2  = (const float*)d_in[19];
    float* out = (float*)d_out;

    // Kernel launches ONLY — graph-capturable. No dynamic smem, no attribute calls.
    fold_kernel<<<1, 256>>>(W0, b0, g0, be0, m0, v0,
                            W1, b1, g1, be1, m1, v1,
                            W2, b2, g2, be2, m2, v2);
    fps_kernel<<<NB, 512>>>(xyz);
    ballquery_kernel<<<(NB * NPOINT) / 8, 256>>>(xyz, out);
    mlp_kernel<<<(NB * NPOINT) / 4, 128>>>(xyz, pts, out);
}